// round 1
// baseline (speedup 1.0000x reference)
#include <cuda_runtime.h>
#include <math.h>

// Problem constants
#define D_    32
#define H_    128
#define B_    64
#define T_    256
#define NSTEP 255          // steps t = 0..254
#define TOUT  252          // outputs for t = 3..254
#define NG    512          // 4 gates * 128
#define SCALE_ATTN 0.17677669529663688f   // 1/sqrt(32)

// ---------------- device scratch (no cudaMalloc allowed) ----------------
__device__ float d_Wcat[D_ * H_ * NG];          // [d][k][n], n = gate*128+h   (8.4 MB)
__device__ float d_Ucat[D_ * NG];               // [d][n]
__device__ float d_Bcat[D_ * NG];               // [d][n]
__device__ float d_qkT[H_ * 256];               // [m][c], c<128 q-col, c>=128 k-col
__device__ float d_vv[4 * H_];                  // [head][m]  (folded V*g2 vectors)
__device__ float d_htraj[(size_t)NSTEP * D_ * B_ * H_];  // [t][d][b][h]  (267 MB)

// ---------------- prep kernels (tiny) ----------------
__global__ void prep_wcat(const float* __restrict__ Wj, const float* __restrict__ Wi,
                          const float* __restrict__ Wf, const float* __restrict__ Wo) {
    int idx = blockIdx.x * 256 + threadIdx.x;          // total 32*128*512
    if (idx >= D_ * H_ * NG) return;
    int n = idx & 511, k = (idx >> 9) & 127, d = idx >> 16;
    int g = n >> 7, h = n & 127;
    const float* W = (g == 0) ? Wj : (g == 1) ? Wi : (g == 2) ? Wf : Wo;
    d_Wcat[idx] = W[(d * H_ + k) * H_ + h];
}

__global__ void prep_ub(const float* __restrict__ Uj, const float* __restrict__ Ui,
                        const float* __restrict__ Uf, const float* __restrict__ Uo,
                        const float* __restrict__ Bj, const float* __restrict__ Bi,
                        const float* __restrict__ Bf, const float* __restrict__ Bo) {
    int idx = blockIdx.x * 256 + threadIdx.x;          // total 32*512
    if (idx >= D_ * NG) return;
    int n = idx & 511, d = idx >> 9;
    int g = n >> 7, h = n & 127;
    const float* U = (g == 0) ? Uj : (g == 1) ? Ui : (g == 2) ? Uf : Uo;
    const float* Bp = (g == 0) ? Bj : (g == 1) ? Bi : (g == 2) ? Bf : Bo;
    d_Ucat[idx] = U[d * H_ + h];    // U_g is (D,1,H) -> [d][h]
    d_Bcat[idx] = Bp[d * H_ + h];
}

// Fold out_w / h_proj_w / w_p into g2, then into per-head vv; also transpose q/k weights.
__global__ void prep_attn(const float* __restrict__ qkv_w, const float* __restrict__ out_w,
                          const float* __restrict__ h_proj_w, const float* __restrict__ w_p) {
    __shared__ float g_s[128];
    __shared__ float g2_s[128];
    int tid = threadIdx.x;  // 128 threads
    float acc = 0.f;
    for (int n = 0; n < 128; n++) acc += h_proj_w[n * 128 + tid] * w_p[n];
    g_s[tid] = acc;
    __syncthreads();
    acc = 0.f;
    for (int hh = 0; hh < 128; hh++) acc += out_w[hh * 128 + tid] * g_s[hh];
    g2_s[tid] = acc;
    __syncthreads();
    // qkT[m][c] = qkv_w[c][m]  for c in [0,256)  (q rows 0..127, k rows 128..255)
    for (int c = 0; c < 256; c++) d_qkT[tid * 256 + c] = qkv_w[c * 128 + tid];
    // vv[head][m] = sum_hd qkv_w[256+head*32+hd][m] * g2[head*32+hd]
    for (int head = 0; head < 4; head++) {
        float a = 0.f;
        for (int hd = 0; hd < 32; hd++)
            a += qkv_w[(256 + head * 32 + hd) * 128 + tid] * g2_s[head * 32 + hd];
        d_vv[head * 128 + tid] = a;
    }
}

// ---------------- phase 1: 255-step recurrence ----------------
// Grid: 128 CTAs = 32 d * 4 batch-tiles of 16.  512 threads = one gate-column n each.
// smem: hT[k][bb] (k-major h state), c state, pre-activation exchange buffer.
__global__ __launch_bounds__(512) void phase1(const float* __restrict__ x) {
    extern __shared__ __align__(16) float smem1[];
    float* hT     = smem1;                 // [128][16]  = 2048
    float* c_sm   = smem1 + 2048;          // [16][128]  = 2048
    float* pre_sm = smem1 + 4096;          // [16][512]  = 8192
    float* xs     = smem1 + 12288;         // [16]

    int d  = blockIdx.x & 31;
    int bt = blockIdx.x >> 5;
    int b0 = bt * 16;
    int n  = threadIdx.x;

    for (int i = n; i < 2048; i += 512) hT[i] = 0.f;
    for (int i = n; i < 2048; i += 512) c_sm[i] = 0.f;

    const float* Wd = d_Wcat + (size_t)d * H_ * NG;
    float u    = d_Ucat[d * NG + n];
    float bias = d_Bcat[d * NG + n];
    __syncthreads();

    for (int t = 0; t < NSTEP; t++) {
        if (n < 16) xs[n] = x[((b0 + n) * T_ + t) * D_ + d];
        __syncthreads();

        float acc[16];
#pragma unroll
        for (int i = 0; i < 16; i++) acc[i] = 0.f;

#pragma unroll 4
        for (int k = 0; k < H_; k++) {
            float w = __ldg(&Wd[k * NG + n]);
            float4 h0 = *(const float4*)&hT[k * 16 + 0];
            float4 h1 = *(const float4*)&hT[k * 16 + 4];
            float4 h2 = *(const float4*)&hT[k * 16 + 8];
            float4 h3 = *(const float4*)&hT[k * 16 + 12];
            acc[0]  += h0.x * w;  acc[1]  += h0.y * w;
            acc[2]  += h0.z * w;  acc[3]  += h0.w * w;
            acc[4]  += h1.x * w;  acc[5]  += h1.y * w;
            acc[6]  += h1.z * w;  acc[7]  += h1.w * w;
            acc[8]  += h2.x * w;  acc[9]  += h2.y * w;
            acc[10] += h2.z * w;  acc[11] += h2.w * w;
            acc[12] += h3.x * w;  acc[13] += h3.y * w;
            acc[14] += h3.z * w;  acc[15] += h3.w * w;
        }
#pragma unroll
        for (int bb = 0; bb < 16; bb++)
            pre_sm[bb * NG + n] = acc[bb] + xs[bb] * u + bias;
        __syncthreads();

        // 2048 (bb,h) cells, 4 per thread: gate nonlinearity + state update
#pragma unroll
        for (int i = 0; i < 4; i++) {
            int cell = n + i * 512;
            int bb = cell >> 7, h = cell & 127;
            float pj = pre_sm[bb * NG + h];
            float pi = pre_sm[bb * NG + 128 + h];
            float pf = pre_sm[bb * NG + 256 + h];
            float po = pre_sm[bb * NG + 384 + h];
            float jj = tanhf(pj);
            float ii = 1.f / (1.f + expf(-pi));
            float ff = 1.f / (1.f + expf(-pf));
            float oo = 1.f / (1.f + expf(-po));
            float c  = c_sm[bb * 128 + h] * ff + ii * jj;
            c_sm[bb * 128 + h] = c;
            float hv = oo * tanhf(c);
            hT[h * 16 + bb] = hv;
            d_htraj[(((size_t)t * D_ + d) * B_ + (b0 + bb)) * H_ + h] = hv;
        }
        __syncthreads();
    }
}

// ---------------- phase 2: attention + folded prediction ----------------
// Grid: (64 b, 252 tt). 256 threads. One CTA computes one scalar pred[b, t].
// Dynamic smem layout (floats):
//   region0 [0,4096)   : hsm[32][128], later reused as scores[4][32][32]
//   q_sm    [4096,8192): [d][c] c<128
//   kT      [8192,12288): [cc][d]  (cc = c-128... stored as kT[cc*32+d]) -> read as kT[(head*32+hd)*32 + j]
//   vg      [12288,12416): [head*32+j]
//   wred    [12416,12424)
#define SMEM2_FLOATS 12424
__global__ __launch_bounds__(256) void phase2(const float* __restrict__ b_p,
                                              float* __restrict__ out) {
    extern __shared__ __align__(16) float smem2[];
    float* region0 = smem2;
    float* q_sm    = smem2 + 4096;
    float* kT      = smem2 + 8192;
    float* vg      = smem2 + 12288;
    float* wred    = smem2 + 12416;

    int b  = blockIdx.x;
    int tt = blockIdx.y;
    int t  = tt + 3;
    int tid = threadIdx.x;

    // load h slab: hsm[d][m]
    for (int i = tid; i < 4096; i += 256) {
        int dd = i >> 7, m = i & 127;
        region0[i] = d_htraj[(((size_t)t * D_ + dd) * B_ + b) * H_ + m];
    }
    __syncthreads();

    // vg[head][j] = h[j][:] . vv[head][:]
    if (tid < 128) {
        int head = tid >> 5, j = tid & 31;
        float a = 0.f;
        const float* hp = &region0[j * 128];
        const float* vp = &d_vv[head * 128];
        for (int m = 0; m < 128; m++) a += hp[m] * vp[m];
        vg[tid] = a;
    }

    // q,k projection: thread owns column c for all 32 d (8 groups of 4)
    {
        int c = tid;
        for (int dg = 0; dg < 8; dg++) {
            float a0 = 0.f, a1 = 0.f, a2 = 0.f, a3 = 0.f;
            const float* h0p = &region0[(dg * 4 + 0) * 128];
            const float* h1p = &region0[(dg * 4 + 1) * 128];
            const float* h2p = &region0[(dg * 4 + 2) * 128];
            const float* h3p = &region0[(dg * 4 + 3) * 128];
#pragma unroll 4
            for (int m = 0; m < 128; m++) {
                float w = __ldg(&d_qkT[m * 256 + c]);
                a0 += h0p[m] * w;
                a1 += h1p[m] * w;
                a2 += h2p[m] * w;
                a3 += h3p[m] * w;
            }
            int d0 = dg * 4;
            if (c < 128) {
                q_sm[(d0 + 0) * 128 + c] = a0;
                q_sm[(d0 + 1) * 128 + c] = a1;
                q_sm[(d0 + 2) * 128 + c] = a2;
                q_sm[(d0 + 3) * 128 + c] = a3;
            } else {
                int cc = c - 128;
                kT[cc * 32 + d0 + 0] = a0;
                kT[cc * 32 + d0 + 1] = a1;
                kT[cc * 32 + d0 + 2] = a2;
                kT[cc * 32 + d0 + 3] = a3;
            }
        }
    }
    __syncthreads();   // hsm no longer needed; q/kT/vg ready

    // scores[head][i][j] overwrite region0
    for (int it = 0; it < 16; it++) {
        int cell = tid + it * 256;
        int head = cell >> 10, i = (cell >> 5) & 31, j = cell & 31;
        const float* qp = &q_sm[i * 128 + head * 32];
        float a = 0.f;
#pragma unroll 8
        for (int hd = 0; hd < 32; hd++)
            a += qp[hd] * kT[(head * 32 + hd) * 32 + j];
        region0[cell] = a * SCALE_ATTN;
    }
    __syncthreads();

    // softmax + threshold + contribution; warp per row group (lane = j)
    int wid = tid >> 5, lane = tid & 31;
    float wsum = 0.f;
    for (int r = 0; r < 16; r++) {
        int row = wid * 16 + r;                 // row = head*32 + i
        int head = row >> 5;
        float s = region0[row * 32 + lane];
        float m = s;
#pragma unroll
        for (int off = 16; off; off >>= 1) m = fmaxf(m, __shfl_xor_sync(0xffffffffu, m, off));
        float e = expf(s - m);
        float sum = e;
#pragma unroll
        for (int off = 16; off; off >>= 1) sum += __shfl_xor_sync(0xffffffffu, sum, off);
        float p = e / sum;
        float contrib = (p >= 0.01f) ? p * vg[head * 32 + lane] : 0.f;
#pragma unroll
        for (int off = 16; off; off >>= 1) contrib += __shfl_xor_sync(0xffffffffu, contrib, off);
        wsum += contrib;
    }
    if (lane == 0) wred[wid] = wsum;
    __syncthreads();
    if (tid == 0) {
        float tot = 0.f;
        for (int w = 0; w < 8; w++) tot += wred[w];
        out[b * TOUT + tt] = tot * (1.f / 32.f) + b_p[0];
    }
}

// ---------------- launch ----------------
extern "C" void kernel_launch(void* const* d_in, const int* in_sizes, int n_in,
                              void* d_out, int out_size) {
    const float* x   = (const float*)d_in[0];
    const float* Uj  = (const float*)d_in[1];
    const float* Ui  = (const float*)d_in[2];
    const float* Uf  = (const float*)d_in[3];
    const float* Uo  = (const float*)d_in[4];
    const float* Wj  = (const float*)d_in[5];
    const float* Wi  = (const float*)d_in[6];
    const float* Wf  = (const float*)d_in[7];
    const float* Wo  = (const float*)d_in[8];
    const float* Bj  = (const float*)d_in[9];
    const float* Bi  = (const float*)d_in[10];
    const float* Bf  = (const float*)d_in[11];
    const float* Bo  = (const float*)d_in[12];
    // d_in[13..24] (mix-LSTM params) are dead code w.r.t. the output
    const float* qkv_w    = (const float*)d_in[25];
    const float* out_w    = (const float*)d_in[26];
    const float* h_proj_w = (const float*)d_in[27];
    const float* w_p      = (const float*)d_in[28];
    const float* b_p      = (const float*)d_in[29];
    float* out = (float*)d_out;

    prep_wcat<<<(D_ * H_ * NG + 255) / 256, 256>>>(Wj, Wi, Wf, Wo);
    prep_ub<<<(D_ * NG + 255) / 256, 256>>>(Uj, Ui, Uf, Uo, Bj, Bi, Bf, Bo);
    prep_attn<<<1, 128>>>(qkv_w, out_w, h_proj_w, w_p);

    int smem1_bytes = (2048 + 2048 + 8192 + 16) * 4;   // 40.3 KB... actually 12304*4 = 49216
    cudaFuncSetAttribute(phase1, cudaFuncAttributeMaxDynamicSharedMemorySize, smem1_bytes);
    phase1<<<128, 512, smem1_bytes>>>(x);

    int smem2_bytes = SMEM2_FLOATS * 4;                // 49696
    cudaFuncSetAttribute(phase2, cudaFuncAttributeMaxDynamicSharedMemorySize, smem2_bytes);
    dim3 g2(B_, TOUT);
    phase2<<<g2, 256, smem2_bytes>>>(b_p, out);
}

// round 4
// speedup vs baseline: 1.9587x; 1.9587x over previous
#include <cuda_runtime.h>
#include <math.h>

// Problem constants
#define D_    32
#define H_    128
#define B_    64
#define T_    256
#define NSTEP 255          // steps t = 0..254
#define TOUT  252          // outputs for t = 3..254
#define NG    512          // 4 gates * 128
#define QKC   264          // 256 q/k cols + 4 vg cols + 4 pad
#define SCALE_ATTN 0.17677669529663688f   // 1/sqrt(32)
#define LOG2E_F 1.4426950408889634f

typedef unsigned long long u64;

// ---------------- device scratch (no cudaMalloc allowed) ----------------
__device__ float d_Wcat[D_ * H_ * NG];                    // [d][k][n]
__device__ float d_Ucat[D_ * NG];
__device__ float d_Bcat[D_ * NG];
__device__ float d_qkT2[H_ * QKC];                        // [m][c]: c<256 q/k, 256..259 folded vv, 260..263 zero
__device__ float d_htraj[(size_t)NSTEP * D_ * B_ * H_];   // [t][d][b][h]
__device__ float d_qkbuf[(size_t)TOUT * D_ * B_ * QKC];   // [tt][d][b][c]

// ---------------- fast math helpers ----------------
__device__ __forceinline__ float fexp2a(float x) {
    float r; asm("ex2.approx.ftz.f32 %0, %1;" : "=f"(r) : "f"(x)); return r;
}
__device__ __forceinline__ float frcpa(float x) {
    float r; asm("rcp.approx.ftz.f32 %0, %1;" : "=f"(r) : "f"(x)); return r;
}
__device__ __forceinline__ float fsigmoid(float x) {
    return frcpa(1.f + fexp2a(-x * LOG2E_F));
}
__device__ __forceinline__ float ftanh(float x) {
    // tanh(x) = 1 - 2/(1+e^{2x});   ex2/rcp approx err ~1e-6 abs
    return fmaf(-2.f, frcpa(1.f + fexp2a(x * (2.f * LOG2E_F))), 1.f);
}
__device__ __forceinline__ void ffma2(u64& d, u64 a, u64 b) {
    asm("fma.rn.f32x2 %0, %1, %2, %0;" : "+l"(d) : "l"(a), "l"(b));
}
__device__ __forceinline__ u64 pack2(float w) {
    u64 r; asm("mov.b64 %0, {%1, %1};" : "=l"(r) : "f"(w)); return r;
}
__device__ __forceinline__ u64 pack2f(float lo, float hi) {
    u64 r; asm("mov.b64 %0, {%1, %2};" : "=l"(r) : "f"(lo), "f"(hi)); return r;
}
__device__ __forceinline__ void unpack2(u64 v, float& lo, float& hi) {
    asm("mov.b64 {%0, %1}, %2;" : "=f"(lo), "=f"(hi) : "l"(v));
}

// ---------------- prep kernels (tiny) ----------------
__global__ void prep_wcat(const float* __restrict__ Wj, const float* __restrict__ Wi,
                          const float* __restrict__ Wf, const float* __restrict__ Wo) {
    int idx = blockIdx.x * 256 + threadIdx.x;
    if (idx >= D_ * H_ * NG) return;
    int n = idx & 511, k = (idx >> 9) & 127, d = idx >> 16;
    int g = n >> 7, h = n & 127;
    const float* W = (g == 0) ? Wj : (g == 1) ? Wi : (g == 2) ? Wf : Wo;
    d_Wcat[idx] = W[(d * H_ + k) * H_ + h];
}

__global__ void prep_ub(const float* __restrict__ Uj, const float* __restrict__ Ui,
                        const float* __restrict__ Uf, const float* __restrict__ Uo,
                        const float* __restrict__ Bj, const float* __restrict__ Bi,
                        const float* __restrict__ Bf, const float* __restrict__ Bo) {
    int idx = blockIdx.x * 256 + threadIdx.x;
    if (idx >= D_ * NG) return;
    int n = idx & 511, d = idx >> 9;
    int g = n >> 7, h = n & 127;
    const float* U = (g == 0) ? Uj : (g == 1) ? Ui : (g == 2) ? Uf : Uo;
    const float* Bp = (g == 0) ? Bj : (g == 1) ? Bi : (g == 2) ? Bf : Bo;
    d_Ucat[idx] = U[d * H_ + h];
    d_Bcat[idx] = Bp[d * H_ + h];
}

// Fold out_w / h_proj_w / w_p -> g2 -> per-head vv columns; transpose q/k weights. 128 threads.
__global__ void prep_attn(const float* __restrict__ qkv_w, const float* __restrict__ out_w,
                          const float* __restrict__ h_proj_w, const float* __restrict__ w_p) {
    __shared__ float g_s[128];
    __shared__ float g2_s[128];
    int tid = threadIdx.x;  // = m
    float acc = 0.f;
    for (int n = 0; n < 128; n++) acc += h_proj_w[n * 128 + tid] * w_p[n];
    g_s[tid] = acc;
    __syncthreads();
    acc = 0.f;
    for (int hh = 0; hh < 128; hh++) acc += out_w[hh * 128 + tid] * g_s[hh];
    g2_s[tid] = acc;
    __syncthreads();
    for (int c = 0; c < 256; c++) d_qkT2[tid * QKC + c] = qkv_w[c * 128 + tid];
    for (int head = 0; head < 4; head++) {
        float a = 0.f;
        for (int hd = 0; hd < 32; hd++)
            a += qkv_w[(256 + head * 32 + hd) * 128 + tid] * g2_s[head * 32 + hd];
        d_qkT2[tid * QKC + 256 + head] = a;
    }
    for (int c = 260; c < QKC; c++) d_qkT2[tid * QKC + c] = 0.f;
}

// ---------------- phase 1: 255-step recurrence ----------------
// 128 CTAs = 32 d * 4 batch-tiles of 16. 512 threads = one gate-column n each.
__global__ __launch_bounds__(512) void phase1(const float* __restrict__ x) {
    extern __shared__ __align__(16) float smem1[];
    float* hT     = smem1;                 // [128][16]
    float* c_sm   = smem1 + 2048;          // [16][128]
    float* pre_sm = smem1 + 4096;          // [16][512]
    float* xs     = smem1 + 12288;         // [16]

    int d  = blockIdx.x & 31;
    int bt = blockIdx.x >> 5;
    int b0 = bt * 16;
    int n  = threadIdx.x;

    for (int i = n; i < 2048; i += 512) hT[i] = 0.f;
    for (int i = n; i < 2048; i += 512) c_sm[i] = 0.f;

    const float* Wd = d_Wcat + (size_t)d * H_ * NG;
    float u    = d_Ucat[d * NG + n];
    float bias = d_Bcat[d * NG + n];
    __syncthreads();

    for (int t = 0; t < NSTEP; t++) {
        if (n < 16) xs[n] = x[((b0 + n) * T_ + t) * D_ + d];
        __syncthreads();

        u64 acc[8];
#pragma unroll
        for (int i = 0; i < 8; i++) acc[i] = 0ull;

#pragma unroll 8
        for (int k = 0; k < H_; k++) {
            u64 ww = pack2(__ldg(&Wd[k * NG + n]));
            const ulonglong2* hp = (const ulonglong2*)&hT[k * 16];
            ulonglong2 p0 = hp[0], p1 = hp[1], p2 = hp[2], p3 = hp[3];
            ffma2(acc[0], p0.x, ww);  ffma2(acc[1], p0.y, ww);
            ffma2(acc[2], p1.x, ww);  ffma2(acc[3], p1.y, ww);
            ffma2(acc[4], p2.x, ww);  ffma2(acc[5], p2.y, ww);
            ffma2(acc[6], p3.x, ww);  ffma2(acc[7], p3.y, ww);
        }
#pragma unroll
        for (int i = 0; i < 8; i++) {
            float lo, hi;
            unpack2(acc[i], lo, hi);
            pre_sm[(2 * i) * NG + n]     = fmaf(xs[2 * i], u, lo + bias);
            pre_sm[(2 * i + 1) * NG + n] = fmaf(xs[2 * i + 1], u, hi + bias);
        }
        __syncthreads();

        // 2048 (bb,h) cells, 4 per thread
#pragma unroll
        for (int i = 0; i < 4; i++) {
            int cell = n + i * 512;
            int bb = cell >> 7, h = cell & 127;
            float pj = pre_sm[bb * NG + h];
            float pi = pre_sm[bb * NG + 128 + h];
            float pf = pre_sm[bb * NG + 256 + h];
            float po = pre_sm[bb * NG + 384 + h];
            float jj = ftanh(pj);
            float ii = fsigmoid(pi);
            float ff = fsigmoid(pf);
            float oo = fsigmoid(po);
            float c  = fmaf(c_sm[bb * 128 + h], ff, ii * jj);
            c_sm[bb * 128 + h] = c;
            float hv = oo * ftanh(c);
            hT[h * 16 + bb] = hv;
            d_htraj[(((size_t)t * D_ + d) * B_ + (b0 + bb)) * H_ + h] = hv;
        }
        __syncthreads();
    }
}

// ---------------- phase 2a: batched q/k/vg projection (GEMM) ----------------
// Grid (bhalf=2, d=32, tt=252), 288 threads; thread = one output column c, 32 rows (batches).
__global__ __launch_bounds__(288) void phase2a() {
    __shared__ __align__(16) float hsT[128 * 36];  // [h][32 rows], stride 36 (16B-aligned rows)

    int b0 = blockIdx.x * 32;
    int d  = blockIdx.y;
    int tt = blockIdx.z;
    int t  = tt + 3;

    const float* src = d_htraj + (((size_t)t * D_ + d) * B_ + b0) * H_;
    for (int i = threadIdx.x; i < 32 * 128; i += 288) {
        int r = i >> 7, h = i & 127;
        hsT[h * 36 + r] = src[r * 128 + h];
    }
    __syncthreads();

    int c = threadIdx.x;
    if (c < QKC) {
        u64 acc[16];
#pragma unroll
        for (int i = 0; i < 16; i++) acc[i] = 0ull;

#pragma unroll 4
        for (int k = 0; k < H_; k++) {
            u64 ww = pack2(__ldg(&d_qkT2[k * QKC + c]));
            const ulonglong2* hp = (const ulonglong2*)&hsT[k * 36];
#pragma unroll
            for (int q = 0; q < 4; q++) {
                ulonglong2 p = hp[q * 2], p2 = hp[q * 2 + 1];
                ffma2(acc[q * 4 + 0], p.x, ww);
                ffma2(acc[q * 4 + 1], p.y, ww);
                ffma2(acc[q * 4 + 2], p2.x, ww);
                ffma2(acc[q * 4 + 3], p2.y, ww);
            }
        }
        float* dst = d_qkbuf + (((size_t)tt * D_ + d) * B_ + b0) * QKC + c;
#pragma unroll
        for (int i = 0; i < 16; i++) {
            float lo, hi;
            unpack2(acc[i], lo, hi);
            dst[(size_t)(2 * i) * QKC]     = lo;
            dst[(size_t)(2 * i + 1) * QKC] = hi;
        }
    }
}

// ---------------- phase 2b: scores + softmax + threshold + folded prediction ----------------
// Grid (b=64, tt=252), 128 threads (4 warps = 4 heads). Lane j = key position (d index).
__global__ __launch_bounds__(128) void phase2b(const float* __restrict__ b_p,
                                               float* __restrict__ out) {
    __shared__ __align__(16) float qk[32 * 266];   // [d][266-padded cols]
    __shared__ float wsum[4];

    int b  = blockIdx.x;
    int tt = blockIdx.y;

    const float* src = d_qkbuf + (((size_t)tt * D_) * B_ + b) * QKC;
    for (int d = 0; d < 32; d++) {
        const float* row = src + (size_t)d * B_ * QKC;
        for (int cc = threadIdx.x; cc < QKC; cc += 128) qk[d * 266 + cc] = row[cc];
    }
    __syncthreads();

    int head = threadIdx.x >> 5, j = threadIdx.x & 31;

    // preload this lane's key row (32 floats) as 16 packed f32x2
    u64 kk[16];
    const float* krow = &qk[j * 266 + 128 + head * 32];
#pragma unroll
    for (int i2 = 0; i2 < 16; i2++) {
        float2 f = *(const float2*)&krow[2 * i2];
        kk[i2] = pack2f(f.x, f.y);
    }
    float vgj = qk[j * 266 + 256 + head];

    float acc = 0.f;
    for (int i = 0; i < 32; i++) {
        const float2* qrow = (const float2*)&qk[i * 266 + head * 32];
        u64 sacc = 0ull;
#pragma unroll
        for (int i2 = 0; i2 < 16; i2++) {
            float2 f = qrow[i2];
            ffma2(sacc, pack2f(f.x, f.y), kk[i2]);
        }
        float lo, hi;
        unpack2(sacc, lo, hi);
        float s = (lo + hi) * SCALE_ATTN;

        float m = s;
#pragma unroll
        for (int off = 16; off; off >>= 1) m = fmaxf(m, __shfl_xor_sync(0xffffffffu, m, off));
        float e = fexp2a((s - m) * LOG2E_F);
        float ssum = e;
#pragma unroll
        for (int off = 16; off; off >>= 1) ssum += __shfl_xor_sync(0xffffffffu, ssum, off);
        float p = e * frcpa(ssum);
        float contrib = (p >= 0.01f) ? p * vgj : 0.f;
#pragma unroll
        for (int off = 16; off; off >>= 1) contrib += __shfl_xor_sync(0xffffffffu, contrib, off);
        acc += contrib;
    }
    if (j == 0) wsum[head] = acc;
    __syncthreads();
    if (threadIdx.x == 0)
        out[b * TOUT + tt] = (wsum[0] + wsum[1] + wsum[2] + wsum[3]) * (1.f / 32.f) + b_p[0];
}

// ---------------- launch ----------------
extern "C" void kernel_launch(void* const* d_in, const int* in_sizes, int n_in,
                              void* d_out, int out_size) {
    const float* x   = (const float*)d_in[0];
    const float* Uj  = (const float*)d_in[1];
    const float* Ui  = (const float*)d_in[2];
    const float* Uf  = (const float*)d_in[3];
    const float* Uo  = (const float*)d_in[4];
    const float* Wj  = (const float*)d_in[5];
    const float* Wi  = (const float*)d_in[6];
    const float* Wf  = (const float*)d_in[7];
    const float* Wo  = (const float*)d_in[8];
    const float* Bj  = (const float*)d_in[9];
    const float* Bi  = (const float*)d_in[10];
    const float* Bf  = (const float*)d_in[11];
    const float* Bo  = (const float*)d_in[12];
    // d_in[13..24] (mix-LSTM params) are dead code w.r.t. the output
    const float* qkv_w    = (const float*)d_in[25];
    const float* out_w    = (const float*)d_in[26];
    const float* h_proj_w = (const float*)d_in[27];
    const float* w_p      = (const float*)d_in[28];
    const float* b_p      = (const float*)d_in[29];
    float* out = (float*)d_out;

    prep_wcat<<<(D_ * H_ * NG + 255) / 256, 256>>>(Wj, Wi, Wf, Wo);
    prep_ub<<<(D_ * NG + 255) / 256, 256>>>(Uj, Ui, Uf, Uo, Bj, Bi, Bf, Bo);
    prep_attn<<<1, 128>>>(qkv_w, out_w, h_proj_w, w_p);

    int smem1_bytes = (2048 + 2048 + 8192 + 16) * 4;
    cudaFuncSetAttribute(phase1, cudaFuncAttributeMaxDynamicSharedMemorySize, smem1_bytes);
    phase1<<<128, 512, smem1_bytes>>>(x);

    dim3 g2a(2, 32, 252);
    phase2a<<<g2a, 288>>>();

    dim3 g2b(B_, TOUT);
    phase2b<<<g2b, 128>>>(b_p, out);
}

// round 5
// speedup vs baseline: 2.0141x; 1.0283x over previous
#include <cuda_runtime.h>
#include <math.h>

// Problem constants
#define D_    32
#define H_    128
#define B_    64
#define T_    256
#define NSTEP 255
#define TOUT  252
#define NG    512
#define QKC   264          // 256 q/k cols + 4 vg cols + 4 pad
#define SCALE_ATTN 0.17677669529663688f
#define LOG2E_F 1.4426950408889634f

typedef unsigned long long u64;

// ---------------- device scratch ----------------
__device__ float d_Wcat2[D_ * H_ * H_ * 4];               // [d][k][h][gate]
__device__ float d_Ucat2[D_ * H_ * 4];                    // [d][h][gate]
__device__ float d_Bcat2[D_ * H_ * 4];                    // [d][h][gate]
__device__ float d_qkT2[H_ * QKC];                        // [m][c]
__device__ float d_htraj[(size_t)NSTEP * D_ * B_ * H_];   // [t][d][b][h]
__device__ float d_qkbuf[(size_t)TOUT * D_ * B_ * QKC];   // [tt][d][b][c]

// ---------------- fast math helpers ----------------
__device__ __forceinline__ float fexp2a(float x) {
    float r; asm("ex2.approx.ftz.f32 %0, %1;" : "=f"(r) : "f"(x)); return r;
}
__device__ __forceinline__ float frcpa(float x) {
    float r; asm("rcp.approx.ftz.f32 %0, %1;" : "=f"(r) : "f"(x)); return r;
}
__device__ __forceinline__ float fsigmoid(float x) {
    return frcpa(1.f + fexp2a(-x * LOG2E_F));
}
__device__ __forceinline__ float ftanh(float x) {
    return fmaf(-2.f, frcpa(1.f + fexp2a(x * (2.f * LOG2E_F))), 1.f);
}
__device__ __forceinline__ void ffma2(u64& d, u64 a, u64 b) {
    asm("fma.rn.f32x2 %0, %1, %2, %0;" : "+l"(d) : "l"(a), "l"(b));
}
__device__ __forceinline__ u64 pack2(float w) {
    u64 r; asm("mov.b64 %0, {%1, %1};" : "=l"(r) : "f"(w)); return r;
}
__device__ __forceinline__ u64 pack2f(float lo, float hi) {
    u64 r; asm("mov.b64 %0, {%1, %2};" : "=l"(r) : "f"(lo), "f"(hi)); return r;
}
__device__ __forceinline__ void unpack2(u64 v, float& lo, float& hi) {
    asm("mov.b64 {%0, %1}, %2;" : "=f"(lo), "=f"(hi) : "l"(v));
}

// ---------------- prep kernels ----------------
__global__ void prep_wcat2(const float* __restrict__ Wj, const float* __restrict__ Wi,
                           const float* __restrict__ Wf, const float* __restrict__ Wo) {
    int idx = blockIdx.x * 256 + threadIdx.x;            // total 32*128*128*4
    if (idx >= D_ * H_ * H_ * 4) return;
    int g = idx & 3, h = (idx >> 2) & 127, k = (idx >> 9) & 127, d = idx >> 16;
    const float* W = (g == 0) ? Wj : (g == 1) ? Wi : (g == 2) ? Wf : Wo;
    d_Wcat2[idx] = W[(d * H_ + k) * H_ + h];
}

__global__ void prep_ub2(const float* __restrict__ Uj, const float* __restrict__ Ui,
                         const float* __restrict__ Uf, const float* __restrict__ Uo,
                         const float* __restrict__ Bj, const float* __restrict__ Bi,
                         const float* __restrict__ Bf, const float* __restrict__ Bo) {
    int idx = blockIdx.x * 256 + threadIdx.x;            // total 32*128*4
    if (idx >= D_ * H_ * 4) return;
    int g = idx & 3, h = (idx >> 2) & 127, d = idx >> 9;
    const float* U = (g == 0) ? Uj : (g == 1) ? Ui : (g == 2) ? Uf : Uo;
    const float* Bp = (g == 0) ? Bj : (g == 1) ? Bi : (g == 2) ? Bf : Bo;
    d_Ucat2[idx] = U[d * H_ + h];
    d_Bcat2[idx] = Bp[d * H_ + h];
}

__global__ void prep_attn(const float* __restrict__ qkv_w, const float* __restrict__ out_w,
                          const float* __restrict__ h_proj_w, const float* __restrict__ w_p) {
    __shared__ float g_s[128];
    __shared__ float g2_s[128];
    int tid = threadIdx.x;  // = m
    float acc = 0.f;
    for (int n = 0; n < 128; n++) acc += h_proj_w[n * 128 + tid] * w_p[n];
    g_s[tid] = acc;
    __syncthreads();
    acc = 0.f;
    for (int hh = 0; hh < 128; hh++) acc += out_w[hh * 128 + tid] * g_s[hh];
    g2_s[tid] = acc;
    __syncthreads();
    for (int c = 0; c < 256; c++) d_qkT2[tid * QKC + c] = qkv_w[c * 128 + tid];
    for (int head = 0; head < 4; head++) {
        float a = 0.f;
        for (int hd = 0; hd < 32; hd++)
            a += qkv_w[(256 + head * 32 + hd) * 128 + tid] * g2_s[head * 32 + hd];
        d_qkT2[tid * QKC + 256 + head] = a;
    }
    for (int c = 260; c < QKC; c++) d_qkT2[tid * QKC + c] = 0.f;
}

// ---------------- phase 1: 255-step recurrence ----------------
// 128 CTAs = 32 d * 4 batch-tiles of 16. 512 threads: h = tid&127, bq = tid>>7.
// Thread owns (h, 4 batches, all 4 gates): no gate exchange, c-state in registers,
// double-buffered hT -> ONE __syncthreads per step.
__global__ __launch_bounds__(512) void phase1(const float* __restrict__ x) {
    __shared__ __align__(16) float hTb[2][H_ * 16];   // [buf][k][16 local batches]
    __shared__ float xs[2][16];

    int d  = blockIdx.x & 31;
    int bt = blockIdx.x >> 5;
    int b0 = bt * 16;
    int tid = threadIdx.x;
    int h  = tid & 127;
    int bq = tid >> 7;           // 0..3 -> local batches bq*4 .. bq*4+3

    // init
    for (int i = tid; i < H_ * 16; i += 512) hTb[0][i] = 0.f;
    if (tid < 16) xs[0][tid] = x[((b0 + tid) * T_ + 0) * D_ + d];

    const float* Wd = d_Wcat2 + (size_t)d * H_ * H_ * 4;
    float4 u4 = *(const float4*)&d_Ucat2[(d * H_ + h) * 4];
    float4 bias4 = *(const float4*)&d_Bcat2[(d * H_ + h) * 4];

    float cc[4] = {0.f, 0.f, 0.f, 0.f};

    for (int t = 0; t < NSTEP; t++) {
        int cur = t & 1, nxt = cur ^ 1;
        __syncthreads();   // hTb[cur], xs[cur] ready

        u64 acc[8];        // [gate*2 + pair]
#pragma unroll
        for (int i = 0; i < 8; i++) acc[i] = 0ull;

        const float* hbase = &hTb[cur][bq * 4];
#pragma unroll 8
        for (int k = 0; k < H_; k++) {
            float4 w4 = __ldg((const float4*)&Wd[(k * H_ + h) * 4]);
            ulonglong2 hp = *(const ulonglong2*)&hbase[k * 16];
            u64 wj = pack2(w4.x), wi = pack2(w4.y), wf = pack2(w4.z), wo = pack2(w4.w);
            ffma2(acc[0], hp.x, wj);  ffma2(acc[1], hp.y, wj);
            ffma2(acc[2], hp.x, wi);  ffma2(acc[3], hp.y, wi);
            ffma2(acc[4], hp.x, wf);  ffma2(acc[5], hp.y, wf);
            ffma2(acc[6], hp.x, wo);  ffma2(acc[7], hp.y, wo);
        }

        float pj[4], pi[4], pf[4], po[4];
        unpack2(acc[0], pj[0], pj[1]);  unpack2(acc[1], pj[2], pj[3]);
        unpack2(acc[2], pi[0], pi[1]);  unpack2(acc[3], pi[2], pi[3]);
        unpack2(acc[4], pf[0], pf[1]);  unpack2(acc[5], pf[2], pf[3]);
        unpack2(acc[6], po[0], po[1]);  unpack2(acc[7], po[2], po[3]);

        float hv[4];
#pragma unroll
        for (int b = 0; b < 4; b++) {
            float xv = xs[cur][bq * 4 + b];
            float jj = ftanh(fmaf(xv, u4.x, pj[b] + bias4.x));
            float ii = fsigmoid(fmaf(xv, u4.y, pi[b] + bias4.y));
            float ff = fsigmoid(fmaf(xv, u4.z, pf[b] + bias4.z));
            float oo = fsigmoid(fmaf(xv, u4.w, po[b] + bias4.w));
            cc[b] = fmaf(cc[b], ff, ii * jj);
            hv[b] = oo * ftanh(cc[b]);
        }
        // write next-step h state (double buffer -> no WAR)
        *(float4*)&hTb[nxt][h * 16 + bq * 4] = make_float4(hv[0], hv[1], hv[2], hv[3]);
        // store trajectory (coalesced per b across warp's 32 consecutive h)
        size_t base = (((size_t)t * D_ + d) * B_ + (b0 + bq * 4)) * H_ + h;
#pragma unroll
        for (int b = 0; b < 4; b++) d_htraj[base + (size_t)b * H_] = hv[b];
        // prefetch next x
        if (tid < 16 && t + 1 < NSTEP) xs[nxt][tid] = x[((b0 + tid) * T_ + (t + 1)) * D_ + d];
    }
}

// ---------------- phase 2a: batched q/k/vg projection ----------------
// Grid (2 bhalf, 32 d, 252 tt), 288 threads: cg = tid>>2 (4 cols), rg = tid&3 (8 rows).
__global__ __launch_bounds__(288) void phase2a() {
    __shared__ __align__(16) float hsT[128 * 36];  // [h][32 rows], stride 36

    int b0 = blockIdx.x * 32;
    int d  = blockIdx.y;
    int tt = blockIdx.z;
    int t  = tt + 3;

    const float* src = d_htraj + (((size_t)t * D_ + d) * B_ + b0) * H_;
    for (int i = threadIdx.x; i < 32 * 128; i += 288) {
        int r = i >> 7, hh = i & 127;
        hsT[hh * 36 + r] = src[r * 128 + hh];
    }
    __syncthreads();

    int cg = threadIdx.x >> 2;       // 0..71, cols cg*4..cg*4+3
    int rg = threadIdx.x & 3;        // rows rg*8..rg*8+7
    if (cg < 66) {
        int c0 = cg * 4;
        u64 acc[16];                 // [col][rowpair]
#pragma unroll
        for (int i = 0; i < 16; i++) acc[i] = 0ull;

        const float* hb = &hsT[rg * 8];
#pragma unroll 4
        for (int k = 0; k < H_; k++) {
            float4 w4 = __ldg((const float4*)&d_qkT2[k * QKC + c0]);
            const ulonglong2* hp = (const ulonglong2*)&hb[k * 36];
            ulonglong2 p0 = hp[0], p1 = hp[1];
            u64 w0 = pack2(w4.x), w1 = pack2(w4.y), w2 = pack2(w4.z), w3 = pack2(w4.w);
            ffma2(acc[0],  p0.x, w0); ffma2(acc[1],  p0.y, w0);
            ffma2(acc[2],  p1.x, w0); ffma2(acc[3],  p1.y, w0);
            ffma2(acc[4],  p0.x, w1); ffma2(acc[5],  p0.y, w1);
            ffma2(acc[6],  p1.x, w1); ffma2(acc[7],  p1.y, w1);
            ffma2(acc[8],  p0.x, w2); ffma2(acc[9],  p0.y, w2);
            ffma2(acc[10], p1.x, w2); ffma2(acc[11], p1.y, w2);
            ffma2(acc[12], p0.x, w3); ffma2(acc[13], p0.y, w3);
            ffma2(acc[14], p1.x, w3); ffma2(acc[15], p1.y, w3);
        }

        float* dst = d_qkbuf + (((size_t)tt * D_ + d) * B_ + b0 + rg * 8) * QKC;
#pragma unroll
        for (int rp = 0; rp < 4; rp++) {
            float v0l, v0h, v1l, v1h, v2l, v2h, v3l, v3h;
            unpack2(acc[rp],      v0l, v0h);
            unpack2(acc[4 + rp],  v1l, v1h);
            unpack2(acc[8 + rp],  v2l, v2h);
            unpack2(acc[12 + rp], v3l, v3h);
            *(float4*)&dst[(size_t)(2 * rp) * QKC + c0]     = make_float4(v0l, v1l, v2l, v3l);
            *(float4*)&dst[(size_t)(2 * rp + 1) * QKC + c0] = make_float4(v0h, v1h, v2h, v3h);
        }
    }
}

// ---------------- phase 2b: scores + softmax + threshold + prediction ----------------
__global__ __launch_bounds__(128) void phase2b(const float* __restrict__ b_p,
                                               float* __restrict__ out) {
    __shared__ __align__(16) float qk[32 * 266];
    __shared__ float wsum[4];

    int b  = blockIdx.x;
    int tt = blockIdx.y;

    const float* src = d_qkbuf + (((size_t)tt * D_) * B_ + b) * QKC;
    for (int d = 0; d < 32; d++) {
        const float* row = src + (size_t)d * B_ * QKC;
        for (int cc = threadIdx.x; cc < QKC; cc += 128) qk[d * 266 + cc] = row[cc];
    }
    __syncthreads();

    int head = threadIdx.x >> 5, j = threadIdx.x & 31;

    u64 kk[16];
    const float* krow = &qk[j * 266 + 128 + head * 32];
#pragma unroll
    for (int i2 = 0; i2 < 16; i2++) {
        float2 f = *(const float2*)&krow[2 * i2];
        kk[i2] = pack2f(f.x, f.y);
    }
    float vgj = qk[j * 266 + 256 + head];

    float acc = 0.f;
    for (int i = 0; i < 32; i++) {
        const float2* qrow = (const float2*)&qk[i * 266 + head * 32];
        u64 sacc = 0ull;
#pragma unroll
        for (int i2 = 0; i2 < 16; i2++) {
            float2 f = qrow[i2];
            ffma2(sacc, pack2f(f.x, f.y), kk[i2]);
        }
        float lo, hi;
        unpack2(sacc, lo, hi);
        float s = (lo + hi) * SCALE_ATTN;

        float m = s;
#pragma unroll
        for (int off = 16; off; off >>= 1) m = fmaxf(m, __shfl_xor_sync(0xffffffffu, m, off));
        float e = fexp2a((s - m) * LOG2E_F);
        float ssum = e;
#pragma unroll
        for (int off = 16; off; off >>= 1) ssum += __shfl_xor_sync(0xffffffffu, ssum, off);
        float p = e * frcpa(ssum);
        float contrib = (p >= 0.01f) ? p * vgj : 0.f;
#pragma unroll
        for (int off = 16; off; off >>= 1) contrib += __shfl_xor_sync(0xffffffffu, contrib, off);
        acc += contrib;
    }
    if (j == 0) wsum[head] = acc;
    __syncthreads();
    if (threadIdx.x == 0)
        out[b * TOUT + tt] = (wsum[0] + wsum[1] + wsum[2] + wsum[3]) * (1.f / 32.f) + b_p[0];
}

// ---------------- launch ----------------
extern "C" void kernel_launch(void* const* d_in, const int* in_sizes, int n_in,
                              void* d_out, int out_size) {
    const float* x   = (const float*)d_in[0];
    const float* Uj  = (const float*)d_in[1];
    const float* Ui  = (const float*)d_in[2];
    const float* Uf  = (const float*)d_in[3];
    const float* Uo  = (const float*)d_in[4];
    const float* Wj  = (const float*)d_in[5];
    const float* Wi  = (const float*)d_in[6];
    const float* Wf  = (const float*)d_in[7];
    const float* Wo  = (const float*)d_in[8];
    const float* Bj  = (const float*)d_in[9];
    const float* Bi  = (const float*)d_in[10];
    const float* Bf  = (const float*)d_in[11];
    const float* Bo  = (const float*)d_in[12];
    // d_in[13..24] dead code
    const float* qkv_w    = (const float*)d_in[25];
    const float* out_w    = (const float*)d_in[26];
    const float* h_proj_w = (const float*)d_in[27];
    const float* w_p      = (const float*)d_in[28];
    const float* b_p      = (const float*)d_in[29];
    float* out = (float*)d_out;

    prep_wcat2<<<(D_ * H_ * H_ * 4 + 255) / 256, 256>>>(Wj, Wi, Wf, Wo);
    prep_ub2<<<(D_ * H_ * 4 + 255) / 256, 256>>>(Uj, Ui, Uf, Uo, Bj, Bi, Bf, Bo);
    prep_attn<<<1, 128>>>(qkv_w, out_w, h_proj_w, w_p);

    phase1<<<128, 512>>>(x);

    dim3 g2a(2, 32, 252);
    phase2a<<<g2a, 288>>>();

    dim3 g2b(B_, TOUT);
    phase2b<<<g2b, 128>>>(b_p, out);
}